// round 1
// baseline (speedup 1.0000x reference)
#include <cuda_runtime.h>
#include <cuda_bf16.h>
#include <math.h>

// Problem constants
#define D_MODEL 4096
#define TWO_D   8192
#define NB      8      // batch
#define SEQ     512    // sequence length (== D_HEAD)
#define LAMBDA_INIT 0.8f

// Scratch in __device__ globals (no runtime allocation allowed)
__device__ float g_q[(size_t)NB * SEQ * TWO_D];      // 134 MB
__device__ float g_k[(size_t)NB * SEQ * TWO_D];      // 134 MB
__device__ float g_v[(size_t)NB * SEQ * TWO_D];      // 134 MB
__device__ float g_l1[(size_t)NB * SEQ * SEQ];       // 8.4 MB
__device__ float g_l2[(size_t)NB * SEQ * SEQ];       // 8.4 MB
__device__ float g_sc[(size_t)NB * SEQ * SEQ];       // 8.4 MB

// ---------------------------------------------------------------------------
// Tiled fp32 SGEMM: 128x128 block tile, BK=16, 256 threads, 8x8 thread tile
// ---------------------------------------------------------------------------
#define BM 128
#define BN 128
#define BK 16
#define TM 8
#define TN 8

// C[M,N] = A[M,K] @ B[N,K]^T (+bias over N).  A row-major lda, B row-major ldb.
__device__ __forceinline__ void sgemm_nk(
    const float* __restrict__ A, int lda,
    const float* __restrict__ Bm, int ldb,
    const float* __restrict__ bias,
    float* __restrict__ C, int ldc,
    int K, int tileM, int tileN)
{
    __shared__ float As[BK][BM];
    __shared__ float Bs[BK][BN];
    const int tid = threadIdx.x;
    const int tn = tid & 15;
    const int tm = tid >> 4;

    float acc[TM][TN];
#pragma unroll
    for (int i = 0; i < TM; i++)
#pragma unroll
        for (int j = 0; j < TN; j++) acc[i][j] = 0.f;

    // Load mapping: 4 lanes per row (coalesced 64B per row), 2 rows per thread
    const int r0 = tid >> 2;            // 0..63
    const int c0 = (tid & 3) * 4;       // 0,4,8,12 within BK
    const float* Ap0 = A + (size_t)(tileM + r0) * lda + c0;
    const float* Ap1 = A + (size_t)(tileM + r0 + 64) * lda + c0;
    const float* Bp0 = Bm + (size_t)(tileN + r0) * ldb + c0;
    const float* Bp1 = Bm + (size_t)(tileN + r0 + 64) * ldb + c0;

    for (int k0 = 0; k0 < K; k0 += BK) {
        float4 a0 = *(const float4*)(Ap0 + k0);
        float4 a1 = *(const float4*)(Ap1 + k0);
        float4 b0 = *(const float4*)(Bp0 + k0);
        float4 b1 = *(const float4*)(Bp1 + k0);
        __syncthreads();
        As[c0 + 0][r0] = a0.x; As[c0 + 1][r0] = a0.y;
        As[c0 + 2][r0] = a0.z; As[c0 + 3][r0] = a0.w;
        As[c0 + 0][r0 + 64] = a1.x; As[c0 + 1][r0 + 64] = a1.y;
        As[c0 + 2][r0 + 64] = a1.z; As[c0 + 3][r0 + 64] = a1.w;
        Bs[c0 + 0][r0] = b0.x; Bs[c0 + 1][r0] = b0.y;
        Bs[c0 + 2][r0] = b0.z; Bs[c0 + 3][r0] = b0.w;
        Bs[c0 + 0][r0 + 64] = b1.x; Bs[c0 + 1][r0 + 64] = b1.y;
        Bs[c0 + 2][r0 + 64] = b1.z; Bs[c0 + 3][r0 + 64] = b1.w;
        __syncthreads();
#pragma unroll
        for (int kk = 0; kk < BK; kk++) {
            float ra[TM], rb[TN];
            *(float4*)&ra[0] = *(const float4*)&As[kk][tm * TM];
            *(float4*)&ra[4] = *(const float4*)&As[kk][tm * TM + 4];
            *(float4*)&rb[0] = *(const float4*)&Bs[kk][tn * TN];
            *(float4*)&rb[4] = *(const float4*)&Bs[kk][tn * TN + 4];
#pragma unroll
            for (int i = 0; i < TM; i++)
#pragma unroll
                for (int j = 0; j < TN; j++)
                    acc[i][j] = fmaf(ra[i], rb[j], acc[i][j]);
        }
    }

#pragma unroll
    for (int i = 0; i < TM; i++) {
        float* crow = C + (size_t)(tileM + tm * TM + i) * ldc + tileN + tn * TN;
        if (bias) {
            const float* brow = bias + tileN + tn * TN;
#pragma unroll
            for (int j = 0; j < TN; j++) crow[j] = acc[i][j] + brow[j];
        } else {
            *(float4*)(crow)     = *(float4*)&acc[i][0];
            *(float4*)(crow + 4) = *(float4*)&acc[i][4];
        }
    }
}

// C[M,N] = A[M,K] @ B[K,N].  B row-major over N (ldb = N stride).
__device__ __forceinline__ void sgemm_kn(
    const float* __restrict__ A, int lda,
    const float* __restrict__ Bm, int ldb,
    float* __restrict__ C, int ldc,
    int K, int tileM, int tileN)
{
    __shared__ float As[BK][BM];
    __shared__ float Bs[BK][BN];
    const int tid = threadIdx.x;
    const int tn = tid & 15;
    const int tm = tid >> 4;

    float acc[TM][TN];
#pragma unroll
    for (int i = 0; i < TM; i++)
#pragma unroll
        for (int j = 0; j < TN; j++) acc[i][j] = 0.f;

    const int r0 = tid >> 2;            // A rows
    const int c0 = (tid & 3) * 4;
    const float* Ap0 = A + (size_t)(tileM + r0) * lda + c0;
    const float* Ap1 = A + (size_t)(tileM + r0 + 64) * lda + c0;

    const int bk = tid >> 5;            // 0..7 : B k-row
    const int bn = (tid & 31) * 4;      // B n-col
    const float* Bp0 = Bm + (size_t)bk * ldb + tileN + bn;
    const float* Bp1 = Bm + (size_t)(bk + 8) * ldb + tileN + bn;

    for (int k0 = 0; k0 < K; k0 += BK) {
        float4 a0 = *(const float4*)(Ap0 + k0);
        float4 a1 = *(const float4*)(Ap1 + k0);
        float4 b0 = *(const float4*)(Bp0 + (size_t)k0 * ldb);
        float4 b1 = *(const float4*)(Bp1 + (size_t)k0 * ldb);
        __syncthreads();
        As[c0 + 0][r0] = a0.x; As[c0 + 1][r0] = a0.y;
        As[c0 + 2][r0] = a0.z; As[c0 + 3][r0] = a0.w;
        As[c0 + 0][r0 + 64] = a1.x; As[c0 + 1][r0 + 64] = a1.y;
        As[c0 + 2][r0 + 64] = a1.z; As[c0 + 3][r0 + 64] = a1.w;
        *(float4*)&Bs[bk][bn]     = b0;
        *(float4*)&Bs[bk + 8][bn] = b1;
        __syncthreads();
#pragma unroll
        for (int kk = 0; kk < BK; kk++) {
            float ra[TM], rb[TN];
            *(float4*)&ra[0] = *(const float4*)&As[kk][tm * TM];
            *(float4*)&ra[4] = *(const float4*)&As[kk][tm * TM + 4];
            *(float4*)&rb[0] = *(const float4*)&Bs[kk][tn * TN];
            *(float4*)&rb[4] = *(const float4*)&Bs[kk][tn * TN + 4];
#pragma unroll
            for (int i = 0; i < TM; i++)
#pragma unroll
                for (int j = 0; j < TN; j++)
                    acc[i][j] = fmaf(ra[i], rb[j], acc[i][j]);
        }
    }

#pragma unroll
    for (int i = 0; i < TM; i++) {
        float* crow = C + (size_t)(tileM + tm * TM + i) * ldc + tileN + tn * TN;
        *(float4*)(crow)     = *(float4*)&acc[i][0];
        *(float4*)(crow + 4) = *(float4*)&acc[i][4];
    }
}

// ---------------------------------------------------------------------------
// Kernels
// ---------------------------------------------------------------------------

// Projection: out = x @ W^T + b.  which: 0=q, 1=k, 2=v.
__global__ void __launch_bounds__(256)
proj_kernel(const float* __restrict__ x, const float* __restrict__ w,
            const float* __restrict__ bias, int which)
{
    float* out = (which == 0) ? g_q : (which == 1) ? g_k : g_v;
    sgemm_nk(x, D_MODEL, w, D_MODEL, bias, out, TWO_D,
             D_MODEL, blockIdx.y * BM, blockIdx.x * BN);
}

// Logits: L_p[b] = Q_p[b] @ K_p[b]^T.  grid.z = b*2 + pair.
__global__ void __launch_bounds__(256)
logits_kernel()
{
    int bz = blockIdx.z;
    int b = bz >> 1, pair = bz & 1;
    const float* A  = g_q + (size_t)b * SEQ * TWO_D + pair * D_MODEL;
    const float* Bm = g_k + (size_t)b * SEQ * TWO_D + pair * D_MODEL;
    float* C = (pair ? g_l2 : g_l1) + (size_t)b * SEQ * SEQ;
    sgemm_nk(A, TWO_D, Bm, TWO_D, nullptr, C, SEQ,
             D_MODEL, blockIdx.y * BM, blockIdx.x * BN);
}

// Softmax over key axis for both logit sets + differential combine:
// scores[b,q,k] = softmax(L1)[k] - lam[k]*softmax(L2)[k]
__global__ void __launch_bounds__(256)
softmax_combine_kernel(const float* __restrict__ lq1, const float* __restrict__ lk1,
                       const float* __restrict__ lq2, const float* __restrict__ lk2)
{
    const int r = blockIdx.x, b = blockIdx.y;
    const size_t off = ((size_t)b * SEQ + r) * SEQ;
    const float scale = 0.04419417382415922f;  // 1/sqrt(512)
    const int tid = threadIdx.x;               // 256 threads, 2 cols each
    const int lane = tid & 31, warp = tid >> 5;

    float v1a = g_l1[off + tid]       * scale;
    float v1b = g_l1[off + tid + 256] * scale;
    float v2a = g_l2[off + tid]       * scale;
    float v2b = g_l2[off + tid + 256] * scale;

    __shared__ float red1[8], red2[8];

    // ---- max ----
    float m1 = fmaxf(v1a, v1b), m2 = fmaxf(v2a, v2b);
#pragma unroll
    for (int o = 16; o; o >>= 1) {
        m1 = fmaxf(m1, __shfl_xor_sync(0xffffffffu, m1, o));
        m2 = fmaxf(m2, __shfl_xor_sync(0xffffffffu, m2, o));
    }
    if (lane == 0) { red1[warp] = m1; red2[warp] = m2; }
    __syncthreads();
    m1 = red1[0]; m2 = red2[0];
#pragma unroll
    for (int i = 1; i < 8; i++) { m1 = fmaxf(m1, red1[i]); m2 = fmaxf(m2, red2[i]); }
    __syncthreads();

    // ---- exp + sum ----
    float e1a = expf(v1a - m1), e1b = expf(v1b - m1);
    float e2a = expf(v2a - m2), e2b = expf(v2b - m2);
    float s1 = e1a + e1b, s2 = e2a + e2b;
#pragma unroll
    for (int o = 16; o; o >>= 1) {
        s1 += __shfl_xor_sync(0xffffffffu, s1, o);
        s2 += __shfl_xor_sync(0xffffffffu, s2, o);
    }
    if (lane == 0) { red1[warp] = s1; red2[warp] = s2; }
    __syncthreads();
    s1 = 0.f; s2 = 0.f;
#pragma unroll
    for (int i = 0; i < 8; i++) { s1 += red1[i]; s2 += red2[i]; }
    const float inv1 = 1.f / s1, inv2 = 1.f / s2;

    // ---- combine with lambda(k) ----
    int k0 = tid, k1 = tid + 256;
    float lam0 = expf(lq1[k0] * lk1[k0]) - expf(lq2[k0] * lk2[k0]) + LAMBDA_INIT;
    float lam1 = expf(lq1[k1] * lk1[k1]) - expf(lq2[k1] * lk2[k1]) + LAMBDA_INIT;
    g_sc[off + k0] = e1a * inv1 - lam0 * (e2a * inv2);
    g_sc[off + k1] = e1b * inv1 - lam1 * (e2b * inv2);
}

// Output: out[b] = scores[b] @ v[b].  grid.z = b.
__global__ void __launch_bounds__(256)
out_gemm_kernel(float* __restrict__ out)
{
    int b = blockIdx.z;
    const float* A  = g_sc + (size_t)b * SEQ * SEQ;
    const float* Bm = g_v  + (size_t)b * SEQ * TWO_D;
    float* C = out + (size_t)b * SEQ * TWO_D;
    sgemm_kn(A, SEQ, Bm, TWO_D, C, TWO_D,
             SEQ, blockIdx.y * BM, blockIdx.x * BN);
}

// ---------------------------------------------------------------------------
extern "C" void kernel_launch(void* const* d_in, const int* in_sizes, int n_in,
                              void* d_out, int out_size)
{
    const float* x    = (const float*)d_in[0];
    const float* wq_w = (const float*)d_in[1];
    const float* wq_b = (const float*)d_in[2];
    const float* wk_w = (const float*)d_in[3];
    const float* wk_b = (const float*)d_in[4];
    const float* wv_w = (const float*)d_in[5];
    const float* wv_b = (const float*)d_in[6];
    const float* lq1  = (const float*)d_in[7];
    const float* lk1  = (const float*)d_in[8];
    const float* lq2  = (const float*)d_in[9];
    const float* lk2  = (const float*)d_in[10];
    float* out = (float*)d_out;

    dim3 projGrid(TWO_D / BN, (NB * SEQ) / BM);          // (64, 32)
    proj_kernel<<<projGrid, 256>>>(x, wq_w, wq_b, 0);
    proj_kernel<<<projGrid, 256>>>(x, wk_w, wk_b, 1);
    proj_kernel<<<projGrid, 256>>>(x, wv_w, wv_b, 2);

    dim3 logitsGrid(SEQ / BN, SEQ / BM, NB * 2);         // (4, 4, 16)
    logits_kernel<<<logitsGrid, 256>>>();

    dim3 smGrid(SEQ, NB);                                // (512, 8)
    softmax_combine_kernel<<<smGrid, 256>>>(lq1, lk1, lq2, lk2);

    dim3 outGrid(TWO_D / BN, SEQ / BM, NB);              // (64, 4, 8)
    out_gemm_kernel<<<outGrid, 256>>>(out);
}

// round 4
// speedup vs baseline: 2.8253x; 2.8253x over previous
#include <cuda_runtime.h>
#include <cuda_bf16.h>
#include <cstdint>
#include <math.h>

// Problem constants
#define D_MODEL 4096
#define TWO_D   8192
#define NB      8
#define SEQ     512
#define LAMBDA_INIT 0.8f

// ---------------------------------------------------------------------------
// Scratch (static device globals; no runtime allocation allowed)
// ---------------------------------------------------------------------------
__device__ __align__(256) __nv_bfloat16 g_xh[(size_t)4096 * 4096];
__device__ __align__(256) __nv_bfloat16 g_xl[(size_t)4096 * 4096];
__device__ __align__(256) __nv_bfloat16 g_wh[(size_t)TWO_D * 4096];   // reused per-proj
__device__ __align__(256) __nv_bfloat16 g_wl[(size_t)TWO_D * 4096];
__device__ __align__(256) __nv_bfloat16 g_qh[(size_t)NB * SEQ * TWO_D];
__device__ __align__(256) __nv_bfloat16 g_ql[(size_t)NB * SEQ * TWO_D];
__device__ __align__(256) __nv_bfloat16 g_kh[(size_t)NB * SEQ * TWO_D];
__device__ __align__(256) __nv_bfloat16 g_kl[(size_t)NB * SEQ * TWO_D];
__device__ __align__(256) float         g_v [(size_t)NB * SEQ * TWO_D];
__device__ __align__(256) __nv_bfloat16 g_vth[(size_t)NB * TWO_D * SEQ];
__device__ __align__(256) __nv_bfloat16 g_vtl[(size_t)NB * TWO_D * SEQ];
__device__ __align__(256) float         g_l1[(size_t)NB * SEQ * SEQ];
__device__ __align__(256) float         g_l2[(size_t)NB * SEQ * SEQ];
__device__ __align__(256) __nv_bfloat16 g_sch[(size_t)NB * SEQ * SEQ];
__device__ __align__(256) __nv_bfloat16 g_scl[(size_t)NB * SEQ * SEQ];

// ---------------------------------------------------------------------------
// PTX primitives (arch-neutral: sm_80+)
// ---------------------------------------------------------------------------
__device__ __forceinline__ uint32_t smem_u32(const void* p) {
    uint32_t a;
    asm("{ .reg .u64 t; cvta.to.shared.u64 t, %1; cvt.u32.u64 %0, t; }"
        : "=r"(a) : "l"(p));
    return a;
}

__device__ __forceinline__ void cpa16(uint32_t dst, const void* src) {
    asm volatile("cp.async.cg.shared.global [%0], [%1], 16;\n"
                 :: "r"(dst), "l"(src));
}
#define CP_COMMIT() asm volatile("cp.async.commit_group;\n" ::: "memory")
#define CP_WAIT(N)  asm volatile("cp.async.wait_group %0;\n" :: "n"(N) : "memory")

#define LDSM4(R, addr) \
    asm volatile("ldmatrix.sync.aligned.m8n8.x4.shared.b16 {%0,%1,%2,%3}, [%4];" \
        : "=r"((R)[0]), "=r"((R)[1]), "=r"((R)[2]), "=r"((R)[3]) : "r"(addr))

__device__ __forceinline__ void mma_bf16(float* c, const uint32_t* a,
                                         uint32_t b0, uint32_t b1) {
    asm volatile(
        "mma.sync.aligned.m16n8k16.row.col.f32.bf16.bf16.f32 "
        "{%0,%1,%2,%3}, {%4,%5,%6,%7}, {%8,%9}, {%0,%1,%2,%3};"
        : "+f"(c[0]), "+f"(c[1]), "+f"(c[2]), "+f"(c[3])
        : "r"(a[0]), "r"(a[1]), "r"(a[2]), "r"(a[3]), "r"(b0), "r"(b1));
}

// Swizzled smem byte offset for tile element row r, 16B-granule g (row = 64B)
__device__ __forceinline__ uint32_t swz(uint32_t r, uint32_t g) {
    return r * 64u + (((g ^ ((r >> 1) & 3u)) << 4));
}

// ---------------------------------------------------------------------------
// GEMM: C[128,128] = A[128,K] @ B[128,K]^T using bf16x3 HMMA
// EPI: 0 = fp32 + bias, 1 = fp32, 2 = bf16 hi/lo + bias
// ---------------------------------------------------------------------------
#define BK       32
#define STAGES   4
#define STAGE_BY 32768            // Ah(8K) Al(8K) Bh(8K) Bl(8K)
#define OFF_AH   0
#define OFF_AL   8192
#define OFF_BH   16384
#define OFF_BL   24576
#define DSMEM_BYTES (STAGES * STAGE_BY + 1024)

template<int EPI>
__device__ __forceinline__ void gemm_body(
    const __nv_bfloat16* __restrict__ Ah, const __nv_bfloat16* __restrict__ Al, int lda,
    const __nv_bfloat16* __restrict__ Bh, const __nv_bfloat16* __restrict__ Bl, int ldb,
    int K,
    float* __restrict__ C, int ldc,
    __nv_bfloat16* __restrict__ Ch, __nv_bfloat16* __restrict__ Cl,
    const float* __restrict__ bias)
{
    extern __shared__ char dsm_raw[];
    const uint32_t sb =
        (smem_u32(dsm_raw) + 1023u) & ~1023u;

    const int tid  = threadIdx.x;
    const int wid  = tid >> 5;
    const int lane = tid & 31;
    const int warp_m = wid & 1;       // 2 in M (64 rows each)
    const int warp_n = wid >> 1;      // 4 in N (32 cols each)

    float acc[4][4][4];
#pragma unroll
    for (int i = 0; i < 4; i++)
#pragma unroll
        for (int j = 0; j < 4; j++)
#pragma unroll
            for (int q = 0; q < 4; q++) acc[i][j][q] = 0.f;

    // cp.async mapping: per tile, granule gid = tid and tid+256; r=gid>>2, g=gid&3
    const int r0g = tid >> 2, g0g = tid & 3;
    const int r1g = (tid + 256) >> 2, g1g = tid & 3;
    const uint32_t d0 = swz(r0g, g0g);
    const uint32_t d1 = swz(r1g, g1g);
    const size_t a0off = (size_t)r0g * lda + g0g * 8;
    const size_t a1off = (size_t)r1g * lda + g1g * 8;
    const size_t b0off = (size_t)r0g * ldb + g0g * 8;
    const size_t b1off = (size_t)r1g * ldb + g1g * 8;

#define LOAD_STAGE(st, kidx) do { \
    const int k0 = (kidx) * BK; \
    const uint32_t sd = sb + (st) * STAGE_BY; \
    cpa16(sd + OFF_AH + d0, Ah + a0off + k0); \
    cpa16(sd + OFF_AH + d1, Ah + a1off + k0); \
    cpa16(sd + OFF_AL + d0, Al + a0off + k0); \
    cpa16(sd + OFF_AL + d1, Al + a1off + k0); \
    cpa16(sd + OFF_BH + d0, Bh + b0off + k0); \
    cpa16(sd + OFF_BH + d1, Bh + b1off + k0); \
    cpa16(sd + OFF_BL + d0, Bl + b0off + k0); \
    cpa16(sd + OFF_BL + d1, Bl + b1off + k0); \
} while (0)

    const int kt = K / BK;
    // Prologue: stages 0..STAGES-2
#pragma unroll
    for (int s = 0; s < STAGES - 1; s++) {
        LOAD_STAGE(s, s);
        CP_COMMIT();
    }

    // ldmatrix lane row/granule assignments
    // A x4: rows m0-7@k0 | m8-15@k0 | m0-7@k8 | m8-15@k8
    const uint32_t a_row = warp_m * 64 + (lane & 7) + (((lane >> 3) & 1) << 3);
    const uint32_t a_gb  = lane >> 4;
    // B x4: n0-7@k0 | n0-7@k8 | n8-15@k0 | n8-15@k8
    const uint32_t b_row = warp_n * 32 + (lane & 7) + ((lane >> 4) << 3);
    const uint32_t b_gb  = (lane >> 3) & 1;

    for (int it = 0; it < kt; it++) {
        CP_WAIT(STAGES - 2);
        __syncthreads();

        const uint32_t st = sb + (it % STAGES) * STAGE_BY;
#pragma unroll
        for (int ks = 0; ks < 2; ks++) {
            uint32_t ah[4][4], al[4][4], bh[2][4], bl[2][4];
            const uint32_t ag = ks * 2 + a_gb;
            const uint32_t bg = ks * 2 + b_gb;
#pragma unroll
            for (int mt = 0; mt < 4; mt++) {
                const uint32_t ad = st + swz(a_row + mt * 16, ag);
                LDSM4(ah[mt], ad + OFF_AH);
                LDSM4(al[mt], ad + OFF_AL);
            }
#pragma unroll
            for (int nt2 = 0; nt2 < 2; nt2++) {
                const uint32_t bd = st + swz(b_row + nt2 * 16, bg);
                LDSM4(bh[nt2], bd + OFF_BH);
                LDSM4(bl[nt2], bd + OFF_BL);
            }
#pragma unroll
            for (int mt = 0; mt < 4; mt++)
#pragma unroll
                for (int nt = 0; nt < 4; nt++) {
                    const int n2 = nt >> 1, o = (nt & 1) * 2;
                    mma_bf16(acc[mt][nt], ah[mt], bh[n2][o], bh[n2][o + 1]);
                    mma_bf16(acc[mt][nt], ah[mt], bl[n2][o], bl[n2][o + 1]);
                    mma_bf16(acc[mt][nt], al[mt], bh[n2][o], bh[n2][o + 1]);
                }
        }
        __syncthreads();
        const int nf = it + STAGES - 1;
        if (nf < kt) LOAD_STAGE(nf % STAGES, nf);
        CP_COMMIT();
    }
#undef LOAD_STAGE

    // Epilogue: lane holds rows (r, r+8) x cols (c, c+1) per mma tile
#pragma unroll
    for (int mt = 0; mt < 4; mt++) {
        const int r = warp_m * 64 + mt * 16 + (lane >> 2);
#pragma unroll
        for (int nt = 0; nt < 4; nt++) {
            const int c = warp_n * 32 + nt * 8 + (lane & 3) * 2;
            float v00 = acc[mt][nt][0], v01 = acc[mt][nt][1];
            float v10 = acc[mt][nt][2], v11 = acc[mt][nt][3];
            if (EPI == 0 || EPI == 2) {
                float2 bb = __ldg((const float2*)(bias + c));
                v00 += bb.x; v01 += bb.y; v10 += bb.x; v11 += bb.y;
            }
            if (EPI == 2) {
                __nv_bfloat16 h0 = __float2bfloat16(v00);
                __nv_bfloat16 h1 = __float2bfloat16(v01);
                __nv_bfloat16 h2 = __float2bfloat16(v10);
                __nv_bfloat16 h3 = __float2bfloat16(v11);
                __nv_bfloat162 p;
                p = __halves2bfloat162(h0, h1);
                *(__nv_bfloat162*)(Ch + (size_t)r * ldc + c) = p;
                p = __halves2bfloat162(h2, h3);
                *(__nv_bfloat162*)(Ch + (size_t)(r + 8) * ldc + c) = p;
                p = __halves2bfloat162(__float2bfloat16(v00 - __bfloat162float(h0)),
                                       __float2bfloat16(v01 - __bfloat162float(h1)));
                *(__nv_bfloat162*)(Cl + (size_t)r * ldc + c) = p;
                p = __halves2bfloat162(__float2bfloat16(v10 - __bfloat162float(h2)),
                                       __float2bfloat16(v11 - __bfloat162float(h3)));
                *(__nv_bfloat162*)(Cl + (size_t)(r + 8) * ldc + c) = p;
            } else {
                float2 s;
                s.x = v00; s.y = v01;
                *(float2*)(C + (size_t)r * ldc + c) = s;
                s.x = v10; s.y = v11;
                *(float2*)(C + (size_t)(r + 8) * ldc + c) = s;
            }
        }
    }
}

// Supertile remap for L2 reuse (G must divide gridDim.y)
__device__ __forceinline__ void remap_xy(int G, int& bx, int& by) {
    int lin = blockIdx.y * gridDim.x + blockIdx.x;
    int per = G * gridDim.x;
    int grp = lin / per, rem = lin % per;
    by = grp * G + (rem % G);
    bx = rem / G;
}

// ---------------------------------------------------------------------------
// GEMM kernels
// ---------------------------------------------------------------------------
__global__ void __launch_bounds__(256, 1)
proj_qk_kernel(const float* __restrict__ bias,
               __nv_bfloat16* __restrict__ Ch, __nv_bfloat16* __restrict__ Cl)
{
    int bx, by; remap_xy(8, bx, by);
    const int tm = by * 128, tn = bx * 128;
    gemm_body<2>(g_xh + (size_t)tm * D_MODEL, g_xl + (size_t)tm * D_MODEL, D_MODEL,
                 g_wh + (size_t)tn * D_MODEL, g_wl + (size_t)tn * D_MODEL, D_MODEL,
                 D_MODEL, nullptr, TWO_D,
                 Ch + (size_t)tm * TWO_D + tn, Cl + (size_t)tm * TWO_D + tn,
                 bias + tn);
}

__global__ void __launch_bounds__(256, 1)
proj_v_kernel(const float* __restrict__ bias)
{
    int bx, by; remap_xy(8, bx, by);
    const int tm = by * 128, tn = bx * 128;
    gemm_body<0>(g_xh + (size_t)tm * D_MODEL, g_xl + (size_t)tm * D_MODEL, D_MODEL,
                 g_wh + (size_t)tn * D_MODEL, g_wl + (size_t)tn * D_MODEL, D_MODEL,
                 D_MODEL, g_v + (size_t)tm * TWO_D + tn, TWO_D,
                 nullptr, nullptr, bias + tn);
}

__global__ void __launch_bounds__(256, 1)
logits_kernel()
{
    const int bz = blockIdx.z;
    const int b = bz >> 1, pair = bz & 1;
    const int tm = blockIdx.y * 128, tn = blockIdx.x * 128;
    const size_t qoff = (size_t)b * SEQ * TWO_D + (size_t)pair * D_MODEL;
    float* C = (pair ? g_l2 : g_l1) + (size_t)b * SEQ * SEQ
             + (size_t)tm * SEQ + tn;
    gemm_body<1>(g_qh + qoff + (size_t)tm * TWO_D, g_ql + qoff + (size_t)tm * TWO_D, TWO_D,
                 g_kh + qoff + (size_t)tn * TWO_D, g_kl + qoff + (size_t)tn * TWO_D, TWO_D,
                 D_MODEL, C, SEQ, nullptr, nullptr, nullptr);
}

__global__ void __launch_bounds__(256, 1)
out_gemm_kernel(float* __restrict__ out)
{
    const int b = blockIdx.z;
    int bx, by; remap_xy(4, bx, by);
    const int tm = by * 128, tn = bx * 128;
    const size_t soff = (size_t)b * SEQ * SEQ + (size_t)tm * SEQ;
    const size_t voff = (size_t)b * TWO_D * SEQ + (size_t)tn * SEQ;
    gemm_body<1>(g_sch + soff, g_scl + soff, SEQ,
                 g_vth + voff, g_vtl + voff, SEQ,
                 SEQ, out + (size_t)b * SEQ * TWO_D + (size_t)tm * TWO_D + tn, TWO_D,
                 nullptr, nullptr, nullptr);
}

// ---------------------------------------------------------------------------
// Support kernels
// ---------------------------------------------------------------------------
__global__ void __launch_bounds__(256)
conv_split_kernel(const float* __restrict__ src,
                  __nv_bfloat16* __restrict__ h, __nv_bfloat16* __restrict__ l,
                  int n4)
{
    int idx = blockIdx.x * 256 + threadIdx.x;
    if (idx >= n4) return;
    float4 v = ((const float4*)src)[idx];
    __nv_bfloat16 hx = __float2bfloat16(v.x);
    __nv_bfloat16 hy = __float2bfloat16(v.y);
    __nv_bfloat16 hz = __float2bfloat16(v.z);
    __nv_bfloat16 hw = __float2bfloat16(v.w);
    __nv_bfloat162* hp = (__nv_bfloat162*)(h + (size_t)idx * 4);
    hp[0] = __halves2bfloat162(hx, hy);
    hp[1] = __halves2bfloat162(hz, hw);
    __nv_bfloat162* lp = (__nv_bfloat162*)(l + (size_t)idx * 4);
    lp[0] = __halves2bfloat162(__float2bfloat16(v.x - __bfloat162float(hx)),
                               __float2bfloat16(v.y - __bfloat162float(hy)));
    lp[1] = __halves2bfloat162(__float2bfloat16(v.z - __bfloat162float(hz)),
                               __float2bfloat16(v.w - __bfloat162float(hw)));
}

// vt[b][n][s] = v[b][s][n], split to bf16 hi/lo
__global__ void __launch_bounds__(256)
transpose_v_kernel()
{
    __shared__ float t[32][33];
    const int b = blockIdx.z;
    const int s0 = blockIdx.y * 32, n0 = blockIdx.x * 32;
    const float* src = g_v + (size_t)b * SEQ * TWO_D;
    const int tx = threadIdx.x, ty = threadIdx.y;
#pragma unroll
    for (int i = ty; i < 32; i += 8)
        t[i][tx] = src[(size_t)(s0 + i) * TWO_D + n0 + tx];
    __syncthreads();
#pragma unroll
    for (int i = ty; i < 32; i += 8) {
        float v = t[tx][i];
        __nv_bfloat16 hh = __float2bfloat16(v);
        size_t o = (size_t)b * TWO_D * SEQ + (size_t)(n0 + i) * SEQ + s0 + tx;
        g_vth[o] = hh;
        g_vtl[o] = __float2bfloat16(v - __bfloat162float(hh));
    }
}

// Softmax over key axis + differential combine; writes bf16 hi/lo scores
__global__ void __launch_bounds__(256)
softmax_combine_kernel(const float* __restrict__ lq1, const float* __restrict__ lk1,
                       const float* __restrict__ lq2, const float* __restrict__ lk2)
{
    const int r = blockIdx.x, b = blockIdx.y;
    const size_t off = ((size_t)b * SEQ + r) * SEQ;
    const float scale = 0.04419417382415922f;  // 1/sqrt(512)
    const int tid = threadIdx.x;
    const int lane = tid & 31, warp = tid >> 5;

    float v1a = g_l1[off + tid]       * scale;
    float v1b = g_l1[off + tid + 256] * scale;
    float v2a = g_l2[off + tid]       * scale;
    float v2b = g_l2[off + tid + 256] * scale;

    __shared__ float red1[8], red2[8];

    float m1 = fmaxf(v1a, v1b), m2 = fmaxf(v2a, v2b);
#pragma unroll
    for (int o = 16; o; o >>= 1) {
        m1 = fmaxf(m1, __shfl_xor_sync(0xffffffffu, m1, o));
        m2 = fmaxf(m2, __shfl_xor_sync(0xffffffffu, m2, o));
    }
    if (lane == 0) { red1[warp] = m1; red2[warp] = m2; }
    __syncthreads();
    m1 = red1[0]; m2 = red2[0];
#pragma unroll
    for (int i = 1; i < 8; i++) { m1 = fmaxf(m1, red1[i]); m2 = fmaxf(m2, red2[i]); }
    __syncthreads();

    float e1a = expf(v1a - m1), e1b = expf(v1b - m1);
    float e2a = expf(v2a - m2), e2b = expf(v2b - m2);
    float s1 = e1a + e1b, s2 = e2a + e2b;
#pragma unroll
    for (int o = 16; o; o >>= 1) {
        s1 += __shfl_xor_sync(0xffffffffu, s1, o);
        s2 += __shfl_xor_sync(0xffffffffu, s2, o);
    }
    if (lane == 0) { red1[warp] = s1; red2[warp] = s2; }
    __syncthreads();
    s1 = 0.f; s2 = 0.f;
#pragma unroll
    for (int i = 0; i < 8; i++) { s1 += red1[i]; s2 += red2[i]; }
    const float inv1 = 1.f / s1, inv2 = 1.f / s2;

#pragma unroll
    for (int half = 0; half < 2; half++) {
        const int k = tid + half * 256;
        float e1 = half ? e1b : e1a;
        float e2 = half ? e2b : e2a;
        float lam = expf(lq1[k] * lk1[k]) - expf(lq2[k] * lk2[k]) + LAMBDA_INIT;
        float v = e1 * inv1 - lam * (e2 * inv2);
        __nv_bfloat16 hh = __float2bfloat16(v);
        g_sch[off + k] = hh;
        g_scl[off + k] = __float2bfloat16(v - __bfloat162float(hh));
    }
}

// ---------------------------------------------------------------------------
extern "C" void kernel_launch(void* const* d_in, const int* in_sizes, int n_in,
                              void* d_out, int out_size)
{
    const float* x    = (const float*)d_in[0];
    const float* wq_w = (const float*)d_in[1];
    const float* wq_b = (const float*)d_in[2];
    const float* wk_w = (const float*)d_in[3];
    const float* wk_b = (const float*)d_in[4];
    const float* wv_w = (const float*)d_in[5];
    const float* wv_b = (const float*)d_in[6];
    const float* lq1  = (const float*)d_in[7];
    const float* lk1  = (const float*)d_in[8];
    const float* lq2  = (const float*)d_in[9];
    const float* lk2  = (const float*)d_in[10];
    float* out = (float*)d_out;

    cudaFuncSetAttribute(proj_qk_kernel,  cudaFuncAttributeMaxDynamicSharedMemorySize, DSMEM_BYTES);
    cudaFuncSetAttribute(proj_v_kernel,   cudaFuncAttributeMaxDynamicSharedMemorySize, DSMEM_BYTES);
    cudaFuncSetAttribute(logits_kernel,   cudaFuncAttributeMaxDynamicSharedMemorySize, DSMEM_BYTES);
    cudaFuncSetAttribute(out_gemm_kernel, cudaFuncAttributeMaxDynamicSharedMemorySize, DSMEM_BYTES);

    __nv_bfloat16 *xh, *xl, *wh, *wl;
    cudaGetSymbolAddress((void**)&xh, g_xh);  // resolve once per launch; cheap host calls
    cudaGetSymbolAddress((void**)&xl, g_xl);
    cudaGetSymbolAddress((void**)&wh, g_wh);
    cudaGetSymbolAddress((void**)&wl, g_wl);
    __nv_bfloat16 *qh, *ql, *kh, *kl;
    cudaGetSymbolAddress((void**)&qh, g_qh);
    cudaGetSymbolAddress((void**)&ql, g_ql);
    cudaGetSymbolAddress((void**)&kh, g_kh);
    cudaGetSymbolAddress((void**)&kl, g_kl);

    const int n4x = 4096 * 4096 / 4;
    const int n4w = TWO_D * 4096 / 4;
    dim3 projGrid(TWO_D / 128, (NB * SEQ) / 128);        // (64, 32)

    conv_split_kernel<<<n4x / 256, 256>>>(x, xh, xl, n4x);

    conv_split_kernel<<<n4w / 256, 256>>>(wq_w, wh, wl, n4w);
    proj_qk_kernel<<<projGrid, 256, DSMEM_BYTES>>>(wq_b, qh, ql);

    conv_split_kernel<<<n4w / 256, 256>>>(wk_w, wh, wl, n4w);
    proj_qk_kernel<<<projGrid, 256, DSMEM_BYTES>>>(wk_b, kh, kl);

    conv_split_kernel<<<n4w / 256, 256>>>(wv_w, wh, wl, n4w);
    proj_v_kernel<<<projGrid, 256, DSMEM_BYTES>>>(wv_b);

    dim3 trGrid(TWO_D / 32, SEQ / 32, NB);
    transpose_v_kernel<<<trGrid, dim3(32, 8)>>>();

    dim3 logitsGrid(SEQ / 128, SEQ / 128, NB * 2);       // (4, 4, 16)
    logits_kernel<<<logitsGrid, 256, DSMEM_BYTES>>>();

    dim3 smGrid(SEQ, NB);
    softmax_combine_kernel<<<smGrid, 256>>>(lq1, lk1, lq2, lk2);

    dim3 outGrid(TWO_D / 128, SEQ / 128, NB);            // (64, 4, 8)
    out_gemm_kernel<<<outGrid, 256, DSMEM_BYTES>>>(out);
}

// round 5
// speedup vs baseline: 3.1641x; 1.1199x over previous
#include <cuda_runtime.h>
#include <cuda_bf16.h>
#include <cstdint>
#include <math.h>

// Problem constants
#define D_MODEL 4096
#define TWO_D   8192
#define NB      8
#define SEQ     512
#define LAMBDA_INIT 0.8f

// ---------------------------------------------------------------------------
// Scratch (static device globals; no runtime allocation allowed)
// ---------------------------------------------------------------------------
__device__ __align__(256) __nv_bfloat16 g_xh [(size_t)4096 * 4096];
__device__ __align__(256) __nv_bfloat16 g_xl [(size_t)4096 * 4096];
__device__ __align__(256) __nv_bfloat16 g_wqh[(size_t)TWO_D * 4096];
__device__ __align__(256) __nv_bfloat16 g_wql[(size_t)TWO_D * 4096];
__device__ __align__(256) __nv_bfloat16 g_wkh[(size_t)TWO_D * 4096];
__device__ __align__(256) __nv_bfloat16 g_wkl[(size_t)TWO_D * 4096];
__device__ __align__(256) __nv_bfloat16 g_wvh[(size_t)TWO_D * 4096];
__device__ __align__(256) __nv_bfloat16 g_wvl[(size_t)TWO_D * 4096];
__device__ __align__(256) __nv_bfloat16 g_qh [(size_t)NB * SEQ * TWO_D];
__device__ __align__(256) __nv_bfloat16 g_ql [(size_t)NB * SEQ * TWO_D];
__device__ __align__(256) __nv_bfloat16 g_kh [(size_t)NB * SEQ * TWO_D];
__device__ __align__(256) __nv_bfloat16 g_kl [(size_t)NB * SEQ * TWO_D];
__device__ __align__(256) float         g_v  [(size_t)NB * SEQ * TWO_D];
__device__ __align__(256) __nv_bfloat16 g_vth[(size_t)NB * TWO_D * SEQ];
__device__ __align__(256) __nv_bfloat16 g_vtl[(size_t)NB * TWO_D * SEQ];
__device__ __align__(256) float         g_l1 [(size_t)NB * SEQ * SEQ];
__device__ __align__(256) float         g_l2 [(size_t)NB * SEQ * SEQ];
__device__ __align__(256) __nv_bfloat16 g_sch[(size_t)NB * SEQ * SEQ];
__device__ __align__(256) __nv_bfloat16 g_scl[(size_t)NB * SEQ * SEQ];

// ---------------------------------------------------------------------------
// PTX primitives (arch-neutral: sm_80+)
// ---------------------------------------------------------------------------
__device__ __forceinline__ uint32_t smem_u32(const void* p) {
    uint32_t a;
    asm("{ .reg .u64 t; cvta.to.shared.u64 t, %1; cvt.u32.u64 %0, t; }"
        : "=r"(a) : "l"(p));
    return a;
}

__device__ __forceinline__ void cpa16(uint32_t dst, const void* src) {
    asm volatile("cp.async.cg.shared.global [%0], [%1], 16;\n"
                 :: "r"(dst), "l"(src));
}
#define CP_COMMIT() asm volatile("cp.async.commit_group;\n" ::: "memory")
#define CP_WAIT(N)  asm volatile("cp.async.wait_group %0;\n" :: "n"(N) : "memory")

#define LDSM4(R, addr) \
    asm volatile("ldmatrix.sync.aligned.m8n8.x4.shared.b16 {%0,%1,%2,%3}, [%4];" \
        : "=r"((R)[0]), "=r"((R)[1]), "=r"((R)[2]), "=r"((R)[3]) : "r"(addr))

__device__ __forceinline__ void mma_bf16(float* c, const uint32_t* a,
                                         uint32_t b0, uint32_t b1) {
    asm volatile(
        "mma.sync.aligned.m16n8k16.row.col.f32.bf16.bf16.f32 "
        "{%0,%1,%2,%3}, {%4,%5,%6,%7}, {%8,%9}, {%0,%1,%2,%3};"
        : "+f"(c[0]), "+f"(c[1]), "+f"(c[2]), "+f"(c[3])
        : "r"(a[0]), "r"(a[1]), "r"(a[2]), "r"(a[3]), "r"(b0), "r"(b1));
}

// Swizzled smem byte offset: tile row r (64B rows), 16B-granule g
__device__ __forceinline__ uint32_t swz(uint32_t r, uint32_t g) {
    return r * 64u + (((g ^ ((r >> 1) & 3u)) << 4));
}

// ---------------------------------------------------------------------------
// GEMM: C[128,256] = A[128,K] @ B[256,K]^T using bf16x3 HMMA
// 256 threads, 8 warps, warp tile 64x64 (2 M-warps x 4 N-warps)
// EPI: 0 = fp32 + bias, 1 = fp32, 2 = bf16 hi/lo + bias
// ---------------------------------------------------------------------------
#define BK       32
#define STAGES   4
#define OFF_AH   0
#define OFF_AL   8192
#define OFF_BH   16384
#define OFF_BL   32768
#define STAGE_BY 49152            // Ah(8K) Al(8K) Bh(16K) Bl(16K)
#define DSMEM_BYTES (STAGES * STAGE_BY + 1024)

template<int EPI>
__device__ __forceinline__ void gemm_body(
    const __nv_bfloat16* __restrict__ Ah, const __nv_bfloat16* __restrict__ Al, int lda,
    const __nv_bfloat16* __restrict__ Bh, const __nv_bfloat16* __restrict__ Bl, int ldb,
    int K,
    float* __restrict__ C, int ldc,
    __nv_bfloat16* __restrict__ Ch, __nv_bfloat16* __restrict__ Cl,
    const float* __restrict__ bias)
{
    extern __shared__ char dsm_raw[];
    const uint32_t sb = (smem_u32(dsm_raw) + 1023u) & ~1023u;

    const int tid  = threadIdx.x;
    const int wid  = tid >> 5;
    const int lane = tid & 31;
    const int warp_m = wid & 1;       // 2 in M (64 rows each)
    const int warp_n = wid >> 1;      // 4 in N (64 cols each)

    float acc[4][8][4];
#pragma unroll
    for (int i = 0; i < 4; i++)
#pragma unroll
        for (int j = 0; j < 8; j++)
#pragma unroll
            for (int q = 0; q < 4; q++) acc[i][j][q] = 0.f;

    // cp.async mapping
    const int rA0 = tid >> 2, gA = tid & 3;
    const uint32_t dA0 = swz(rA0, gA), dA1 = swz(rA0 + 64, gA);
    const size_t aoff0 = (size_t)rA0 * lda + gA * 8;
    const size_t aoff1 = (size_t)(rA0 + 64) * lda + gA * 8;
    uint32_t dB[4];
    size_t boff[4];
#pragma unroll
    for (int j = 0; j < 4; j++) {
        const int r = rA0 + 64 * j;
        dB[j] = swz(r, gA);
        boff[j] = (size_t)r * ldb + gA * 8;
    }

#define LOAD_STAGE(st, kidx) do { \
    const int k0 = (kidx) * BK; \
    const uint32_t sd = sb + (st) * STAGE_BY; \
    cpa16(sd + OFF_AH + dA0, Ah + aoff0 + k0); \
    cpa16(sd + OFF_AH + dA1, Ah + aoff1 + k0); \
    cpa16(sd + OFF_AL + dA0, Al + aoff0 + k0); \
    cpa16(sd + OFF_AL + dA1, Al + aoff1 + k0); \
    cpa16(sd + OFF_BH + dB[0], Bh + boff[0] + k0); \
    cpa16(sd + OFF_BH + dB[1], Bh + boff[1] + k0); \
    cpa16(sd + OFF_BH + dB[2], Bh + boff[2] + k0); \
    cpa16(sd + OFF_BH + dB[3], Bh + boff[3] + k0); \
    cpa16(sd + OFF_BL + dB[0], Bl + boff[0] + k0); \
    cpa16(sd + OFF_BL + dB[1], Bl + boff[1] + k0); \
    cpa16(sd + OFF_BL + dB[2], Bl + boff[2] + k0); \
    cpa16(sd + OFF_BL + dB[3], Bl + boff[3] + k0); \
} while (0)

    const int kt = K / BK;
#pragma unroll
    for (int s = 0; s < STAGES - 1; s++) {
        LOAD_STAGE(s, s);
        CP_COMMIT();
    }

    // ldmatrix lane assignments (same layout as validated 128x128 version)
    const uint32_t a_row = warp_m * 64 + (lane & 7) + (((lane >> 3) & 1) << 3);
    const uint32_t a_gb  = lane >> 4;
    const uint32_t b_row = warp_n * 64 + (lane & 7) + ((lane >> 4) << 3);
    const uint32_t b_gb  = (lane >> 3) & 1;

    for (int it = 0; it < kt; it++) {
        CP_WAIT(STAGES - 2);
        __syncthreads();

        // issue next-stage loads right after the barrier (overlap with compute)
        const int nf = it + STAGES - 1;
        if (nf < kt) LOAD_STAGE(nf % STAGES, nf);
        CP_COMMIT();

        const uint32_t st = sb + (it % STAGES) * STAGE_BY;
#pragma unroll
        for (int ks = 0; ks < 2; ks++) {
            const uint32_t ag = ks * 2 + a_gb;
            const uint32_t bg = ks * 2 + b_gb;
            uint32_t ah[4][4], al[4][4];
#pragma unroll
            for (int mt = 0; mt < 4; mt++) {
                const uint32_t ad = st + swz(a_row + mt * 16, ag);
                LDSM4(ah[mt], ad + OFF_AH);
                LDSM4(al[mt], ad + OFF_AL);
            }
#pragma unroll
            for (int nc = 0; nc < 4; nc++) {        // 4 chunks of n16
                uint32_t bh[4], bl[4];
                const uint32_t bd = st + swz(b_row + nc * 16, bg);
                LDSM4(bh, bd + OFF_BH);
                LDSM4(bl, bd + OFF_BL);
#pragma unroll
                for (int mt = 0; mt < 4; mt++)
#pragma unroll
                    for (int h = 0; h < 2; h++) {   // n8 halves of the n16 chunk
                        float* a4 = acc[mt][nc * 2 + h];
                        mma_bf16(a4, ah[mt], bh[h * 2], bh[h * 2 + 1]);
                        mma_bf16(a4, ah[mt], bl[h * 2], bl[h * 2 + 1]);
                        mma_bf16(a4, al[mt], bh[h * 2], bh[h * 2 + 1]);
                    }
            }
        }
    }
#undef LOAD_STAGE

    // Epilogue
#pragma unroll
    for (int mt = 0; mt < 4; mt++) {
        const int r = warp_m * 64 + mt * 16 + (lane >> 2);
#pragma unroll
        for (int nt = 0; nt < 8; nt++) {
            const int c = warp_n * 64 + nt * 8 + (lane & 3) * 2;
            float v00 = acc[mt][nt][0], v01 = acc[mt][nt][1];
            float v10 = acc[mt][nt][2], v11 = acc[mt][nt][3];
            if (EPI == 0 || EPI == 2) {
                float2 bb = __ldg((const float2*)(bias + c));
                v00 += bb.x; v01 += bb.y; v10 += bb.x; v11 += bb.y;
            }
            if (EPI == 2) {
                __nv_bfloat16 h0 = __float2bfloat16(v00);
                __nv_bfloat16 h1 = __float2bfloat16(v01);
                __nv_bfloat16 h2 = __float2bfloat16(v10);
                __nv_bfloat16 h3 = __float2bfloat16(v11);
                *(__nv_bfloat162*)(Ch + (size_t)r * ldc + c) = __halves2bfloat162(h0, h1);
                *(__nv_bfloat162*)(Ch + (size_t)(r + 8) * ldc + c) = __halves2bfloat162(h2, h3);
                *(__nv_bfloat162*)(Cl + (size_t)r * ldc + c) =
                    __halves2bfloat162(__float2bfloat16(v00 - __bfloat162float(h0)),
                                       __float2bfloat16(v01 - __bfloat162float(h1)));
                *(__nv_bfloat162*)(Cl + (size_t)(r + 8) * ldc + c) =
                    __halves2bfloat162(__float2bfloat16(v10 - __bfloat162float(h2)),
                                       __float2bfloat16(v11 - __bfloat162float(h3)));
            } else {
                float2 s;
                s.x = v00; s.y = v01;
                *(float2*)(C + (size_t)r * ldc + c) = s;
                s.x = v10; s.y = v11;
                *(float2*)(C + (size_t)(r + 8) * ldc + c) = s;
            }
        }
    }
}

// Supertile remap for L2 reuse (G must divide gridDim.y)
__device__ __forceinline__ void remap_xy(int G, int& bx, int& by) {
    int lin = blockIdx.y * gridDim.x + blockIdx.x;
    int per = G * gridDim.x;
    int grp = lin / per, rem = lin % per;
    by = grp * G + (rem % G);
    bx = rem / G;
}

// ---------------------------------------------------------------------------
// GEMM kernels (CTA tile 128M x 256N)
// ---------------------------------------------------------------------------
__global__ void __launch_bounds__(256, 1)
proj_qk_kernel(const __nv_bfloat16* __restrict__ Wh, const __nv_bfloat16* __restrict__ Wl,
               const float* __restrict__ bias,
               __nv_bfloat16* __restrict__ Ch, __nv_bfloat16* __restrict__ Cl)
{
    int bx, by; remap_xy(8, bx, by);
    const int tm = by * 128, tn = bx * 256;
    gemm_body<2>(g_xh + (size_t)tm * D_MODEL, g_xl + (size_t)tm * D_MODEL, D_MODEL,
                 Wh + (size_t)tn * D_MODEL, Wl + (size_t)tn * D_MODEL, D_MODEL,
                 D_MODEL, nullptr, TWO_D,
                 Ch + (size_t)tm * TWO_D + tn, Cl + (size_t)tm * TWO_D + tn,
                 bias + tn);
}

__global__ void __launch_bounds__(256, 1)
proj_v_kernel(const float* __restrict__ bias)
{
    int bx, by; remap_xy(8, bx, by);
    const int tm = by * 128, tn = bx * 256;
    gemm_body<0>(g_xh + (size_t)tm * D_MODEL, g_xl + (size_t)tm * D_MODEL, D_MODEL,
                 g_wvh + (size_t)tn * D_MODEL, g_wvl + (size_t)tn * D_MODEL, D_MODEL,
                 D_MODEL, g_v + (size_t)tm * TWO_D + tn, TWO_D,
                 nullptr, nullptr, bias + tn);
}

__global__ void __launch_bounds__(256, 1)
logits_kernel()
{
    const int bz = blockIdx.z;
    const int b = bz >> 1, pair = bz & 1;
    const int tm = blockIdx.y * 128, tn = blockIdx.x * 256;
    const size_t qoff = (size_t)b * SEQ * TWO_D + (size_t)pair * D_MODEL;
    float* C = (pair ? g_l2 : g_l1) + (size_t)b * SEQ * SEQ
             + (size_t)tm * SEQ + tn;
    gemm_body<1>(g_qh + qoff + (size_t)tm * TWO_D, g_ql + qoff + (size_t)tm * TWO_D, TWO_D,
                 g_kh + qoff + (size_t)tn * TWO_D, g_kl + qoff + (size_t)tn * TWO_D, TWO_D,
                 D_MODEL, C, SEQ, nullptr, nullptr, nullptr);
}

__global__ void __launch_bounds__(256, 1)
out_gemm_kernel(float* __restrict__ out)
{
    const int b = blockIdx.z;
    int bx, by; remap_xy(4, bx, by);
    const int tm = by * 128, tn = bx * 256;
    const size_t soff = (size_t)b * SEQ * SEQ + (size_t)tm * SEQ;
    const size_t voff = (size_t)b * TWO_D * SEQ + (size_t)tn * SEQ;
    gemm_body<1>(g_sch + soff, g_scl + soff, SEQ,
                 g_vth + voff, g_vtl + voff, SEQ,
                 SEQ, out + (size_t)b * SEQ * TWO_D + (size_t)tm * TWO_D + tn, TWO_D,
                 nullptr, nullptr, nullptr);
}

// ---------------------------------------------------------------------------
// Support kernels
// ---------------------------------------------------------------------------
__global__ void __launch_bounds__(256)
conv_split_kernel(const float* __restrict__ src,
                  __nv_bfloat16* __restrict__ h, __nv_bfloat16* __restrict__ l,
                  int n4)
{
    int idx = blockIdx.x * 256 + threadIdx.x;
    if (idx >= n4) return;
    float4 v = ((const float4*)src)[idx];
    __nv_bfloat16 hx = __float2bfloat16(v.x);
    __nv_bfloat16 hy = __float2bfloat16(v.y);
    __nv_bfloat16 hz = __float2bfloat16(v.z);
    __nv_bfloat16 hw = __float2bfloat16(v.w);
    __nv_bfloat162* hp = (__nv_bfloat162*)(h + (size_t)idx * 4);
    hp[0] = __halves2bfloat162(hx, hy);
    hp[1] = __halves2bfloat162(hz, hw);
    __nv_bfloat162* lp = (__nv_bfloat162*)(l + (size_t)idx * 4);
    lp[0] = __halves2bfloat162(__float2bfloat16(v.x - __bfloat162float(hx)),
                               __float2bfloat16(v.y - __bfloat162float(hy)));
    lp[1] = __halves2bfloat162(__float2bfloat16(v.z - __bfloat162float(hz)),
                               __float2bfloat16(v.w - __bfloat162float(hw)));
}

// vt[b][n][s] = v[b][s][n], split to bf16 hi/lo
__global__ void __launch_bounds__(256)
transpose_v_kernel()
{
    __shared__ float t[32][33];
    const int b = blockIdx.z;
    const int s0 = blockIdx.y * 32, n0 = blockIdx.x * 32;
    const float* src = g_v + (size_t)b * SEQ * TWO_D;
    const int tx = threadIdx.x, ty = threadIdx.y;
#pragma unroll
    for (int i = ty; i < 32; i += 8)
        t[i][tx] = src[(size_t)(s0 + i) * TWO_D + n0 + tx];
    __syncthreads();
#pragma unroll
    for (int i = ty; i < 32; i += 8) {
        float v = t[tx][i];
        __nv_bfloat16 hh = __float2bfloat16(v);
        size_t o = (size_t)b * TWO_D * SEQ + (size_t)(n0 + i) * SEQ + s0 + tx;
        g_vth[o] = hh;
        g_vtl[o] = __float2bfloat16(v - __bfloat162float(hh));
    }
}

// Softmax over key axis + differential combine; writes bf16 hi/lo scores
__global__ void __launch_bounds__(256)
softmax_combine_kernel(const float* __restrict__ lq1, const float* __restrict__ lk1,
                       const float* __restrict__ lq2, const float* __restrict__ lk2)
{
    const int r = blockIdx.x, b = blockIdx.y;
    const size_t off = ((size_t)b * SEQ + r) * SEQ;
    const float scale = 0.04419417382415922f;  // 1/sqrt(512)
    const int tid = threadIdx.x;
    const int lane = tid & 31, warp = tid >> 5;

    float v1a = g_l1[off + tid]       * scale;
    float v1b = g_l1[off + tid + 256] * scale;
    float v2a = g_l2[off + tid]       * scale;
    float v2b = g_l2[off + tid + 256] * scale;

    __shared__ float red1[8], red2[8];

    float m1 = fmaxf(v1a, v1b), m2 = fmaxf(v2a, v2b);
#pragma unroll
    for (int o = 16; o; o >>= 1) {
        m1 = fmaxf(m1, __shfl_xor_sync(0xffffffffu, m1, o));
        m2 = fmaxf(m2, __shfl_xor_sync(0xffffffffu, m2, o));
    }
    if (lane == 0) { red1[warp] = m1; red2[warp] = m2; }
    __syncthreads();
    m1 = red1[0]; m2 = red2[0];
#pragma unroll
    for (int i = 1; i < 8; i++) { m1 = fmaxf(m1, red1[i]); m2 = fmaxf(m2, red2[i]); }
    __syncthreads();

    float e1a = expf(v1a - m1), e1b = expf(v1b - m1);
    float e2a = expf(v2a - m2), e2b = expf(v2b - m2);
    float s1 = e1a + e1b, s2 = e2a + e2b;
#pragma unroll
    for (int o = 16; o; o >>= 1) {
        s1 += __shfl_xor_sync(0xffffffffu, s1, o);
        s2 += __shfl_xor_sync(0xffffffffu, s2, o);
    }
    if (lane == 0) { red1[warp] = s1; red2[warp] = s2; }
    __syncthreads();
    s1 = 0.f; s2 = 0.f;
#pragma unroll
    for (int i = 0; i < 8; i++) { s1 += red1[i]; s2 += red2[i]; }
    const float inv1 = 1.f / s1, inv2 = 1.f / s2;

#pragma unroll
    for (int half = 0; half < 2; half++) {
        const int k = tid + half * 256;
        float e1 = half ? e1b : e1a;
        float e2 = half ? e2b : e2a;
        float lam = expf(lq1[k] * lk1[k]) - expf(lq2[k] * lk2[k]) + LAMBDA_INIT;
        float v = e1 * inv1 - lam * (e2 * inv2);
        __nv_bfloat16 hh = __float2bfloat16(v);
        g_sch[off + k] = hh;
        g_scl[off + k] = __float2bfloat16(v - __bfloat162float(hh));
    }
}

// ---------------------------------------------------------------------------
extern "C" void kernel_launch(void* const* d_in, const int* in_sizes, int n_in,
                              void* d_out, int out_size)
{
    const float* x    = (const float*)d_in[0];
    const float* wq_w = (const float*)d_in[1];
    const float* wq_b = (const float*)d_in[2];
    const float* wk_w = (const float*)d_in[3];
    const float* wk_b = (const float*)d_in[4];
    const float* wv_w = (const float*)d_in[5];
    const float* wv_b = (const float*)d_in[6];
    const float* lq1  = (const float*)d_in[7];
    const float* lk1  = (const float*)d_in[8];
    const float* lq2  = (const float*)d_in[9];
    const float* lk2  = (const float*)d_in[10];
    float* out = (float*)d_out;

    cudaFuncSetAttribute(proj_qk_kernel,  cudaFuncAttributeMaxDynamicSharedMemorySize, DSMEM_BYTES);
    cudaFuncSetAttribute(proj_v_kernel,   cudaFuncAttributeMaxDynamicSharedMemorySize, DSMEM_BYTES);
    cudaFuncSetAttribute(logits_kernel,   cudaFuncAttributeMaxDynamicSharedMemorySize, DSMEM_BYTES);
    cudaFuncSetAttribute(out_gemm_kernel, cudaFuncAttributeMaxDynamicSharedMemorySize, DSMEM_BYTES);

    __nv_bfloat16 *xh, *xl, *wqh, *wql, *wkh, *wkl, *wvh, *wvl;
    cudaGetSymbolAddress((void**)&xh,  g_xh);
    cudaGetSymbolAddress((void**)&xl,  g_xl);
    cudaGetSymbolAddress((void**)&wqh, g_wqh);
    cudaGetSymbolAddress((void**)&wql, g_wql);
    cudaGetSymbolAddress((void**)&wkh, g_wkh);
    cudaGetSymbolAddress((void**)&wkl, g_wkl);
    cudaGetSymbolAddress((void**)&wvh, g_wvh);
    cudaGetSymbolAddress((void**)&wvl, g_wvl);
    __nv_bfloat16 *qh, *ql, *kh, *kl;
    cudaGetSymbolAddress((void**)&qh, g_qh);
    cudaGetSymbolAddress((void**)&ql, g_ql);
    cudaGetSymbolAddress((void**)&kh, g_kh);
    cudaGetSymbolAddress((void**)&kl, g_kl);

    const int n4x = 4096 * 4096 / 4;
    const int n4w = TWO_D * 4096 / 4;

    // All conversions first (also puts a proj GEMM at ncu's profiled launch #5)
    conv_split_kernel<<<n4x / 256, 256>>>(x, xh, xl, n4x);          // 0
    conv_split_kernel<<<n4w / 256, 256>>>(wq_w, wqh, wql, n4w);     // 1
    conv_split_kernel<<<n4w / 256, 256>>>(wk_w, wkh, wkl, n4w);     // 2
    conv_split_kernel<<<n4w / 256, 256>>>(wv_w, wvh, wvl, n4w);     // 3

    dim3 projGrid(TWO_D / 256, (NB * SEQ) / 128);                   // (32, 32)
    proj_qk_kernel<<<projGrid, 256, DSMEM_BYTES>>>(wqh, wql, wq_b, qh, ql);  // 4
    proj_qk_kernel<<<projGrid, 256, DSMEM_BYTES>>>(wkh, wkl, wk_b, kh, kl);  // 5 <- profiled
    proj_v_kernel<<<projGrid, 256, DSMEM_BYTES>>>(wv_b);                     // 6

    dim3 trGrid(TWO_D / 32, SEQ / 32, NB);
    transpose_v_kernel<<<trGrid, dim3(32, 8)>>>();

    dim3 logitsGrid(SEQ / 256, SEQ / 128, NB * 2);                  // (2, 4, 16)
    logits_kernel<<<logitsGrid, 256, DSMEM_BYTES>>>();

    dim3 smGrid(SEQ, NB);
    softmax_combine_kernel<<<smGrid, 256>>>(lq1, lk1, lq2, lk2);

    dim3 outGrid(TWO_D / 256, SEQ / 128, NB);                       // (32, 4, 8)
    out_gemm_kernel<<<outGrid, 256, DSMEM_BYTES>>>(out);
}

// round 6
// speedup vs baseline: 4.2321x; 1.3376x over previous
#include <cuda_runtime.h>
#include <cuda_fp16.h>
#include <cstdint>
#include <math.h>

// Problem constants
#define D_MODEL 4096
#define TWO_D   8192
#define NB      8
#define SEQ     512
#define LAMBDA_INIT 0.8f

// ---------------------------------------------------------------------------
// Scratch (static device globals; no runtime allocation allowed)
// A-side operands: hi only. B-side operands: hi + lo.
// ---------------------------------------------------------------------------
__device__ __align__(256) __half g_xh [(size_t)4096 * 4096];
__device__ __align__(256) __half g_wqh[(size_t)TWO_D * 4096];
__device__ __align__(256) __half g_wql[(size_t)TWO_D * 4096];
__device__ __align__(256) __half g_wkh[(size_t)TWO_D * 4096];
__device__ __align__(256) __half g_wkl[(size_t)TWO_D * 4096];
__device__ __align__(256) __half g_wvh[(size_t)TWO_D * 4096];
__device__ __align__(256) __half g_wvl[(size_t)TWO_D * 4096];
__device__ __align__(256) __half g_qh [(size_t)NB * SEQ * TWO_D];
__device__ __align__(256) __half g_kh [(size_t)NB * SEQ * TWO_D];
__device__ __align__(256) __half g_kl [(size_t)NB * SEQ * TWO_D];
__device__ __align__(256) float  g_v  [(size_t)NB * SEQ * TWO_D];
__device__ __align__(256) __half g_vth[(size_t)NB * TWO_D * SEQ];
__device__ __align__(256) __half g_vtl[(size_t)NB * TWO_D * SEQ];
__device__ __align__(256) float  g_l1 [(size_t)NB * SEQ * SEQ];
__device__ __align__(256) float  g_l2 [(size_t)NB * SEQ * SEQ];
__device__ __align__(256) __half g_sch[(size_t)NB * SEQ * SEQ];

// ---------------------------------------------------------------------------
// PTX primitives (arch-neutral: sm_80+)
// ---------------------------------------------------------------------------
__device__ __forceinline__ uint32_t smem_u32(const void* p) {
    uint32_t a;
    asm("{ .reg .u64 t; cvta.to.shared.u64 t, %1; cvt.u32.u64 %0, t; }"
        : "=r"(a) : "l"(p));
    return a;
}

__device__ __forceinline__ void cpa16(uint32_t dst, const void* src) {
    asm volatile("cp.async.cg.shared.global [%0], [%1], 16;\n"
                 :: "r"(dst), "l"(src));
}
#define CP_COMMIT() asm volatile("cp.async.commit_group;\n" ::: "memory")
#define CP_WAIT(N)  asm volatile("cp.async.wait_group %0;\n" :: "n"(N) : "memory")

#define LDSM4(R, addr) \
    asm volatile("ldmatrix.sync.aligned.m8n8.x4.shared.b16 {%0,%1,%2,%3}, [%4];" \
        : "=r"((R)[0]), "=r"((R)[1]), "=r"((R)[2]), "=r"((R)[3]) : "r"(addr))

__device__ __forceinline__ void mma_f16(float* c, const uint32_t* a,
                                        uint32_t b0, uint32_t b1) {
    asm volatile(
        "mma.sync.aligned.m16n8k16.row.col.f32.f16.f16.f32 "
        "{%0,%1,%2,%3}, {%4,%5,%6,%7}, {%8,%9}, {%0,%1,%2,%3};"
        : "+f"(c[0]), "+f"(c[1]), "+f"(c[2]), "+f"(c[3])
        : "r"(a[0]), "r"(a[1]), "r"(a[2]), "r"(a[3]), "r"(b0), "r"(b1));
}

// Swizzled smem byte offset: tile row r (64B rows), 16B-granule g
__device__ __forceinline__ uint32_t swz(uint32_t r, uint32_t g) {
    return r * 64u + (((g ^ ((r >> 1) & 3u)) << 4));
}

__device__ __forceinline__ __half2 split_hl(float a, float b, __half2& lo) {
    __half ha = __float2half_rn(a), hb = __float2half_rn(b);
    lo = __halves2half2(__float2half_rn(a - __half2float(ha)),
                        __float2half_rn(b - __half2float(hb)));
    return __halves2half2(ha, hb);
}

// ---------------------------------------------------------------------------
// GEMM: C[128,256] = A[128,K] @ B[256,K]^T, fp16 2-product split
// (A hi-only; B hi+lo; dropped Al*Bh term ~1.4e-4 relative)
// 256 threads, 8 warps, warp tile 64x64 (2 M-warps x 4 N-warps)
// EPI: 0 = fp32 + bias, 1 = fp32, 2 = f16 hi/lo + bias, 3 = f16 hi + bias
// ---------------------------------------------------------------------------
#define BK       32
#define STAGES   4
#define OFF_AH   0
#define OFF_BH   8192
#define OFF_BL   24576
#define STAGE_BY 40960            // Ah(8K) Bh(16K) Bl(16K)
#define DSMEM_BYTES (STAGES * STAGE_BY + 1024)

template<int EPI>
__device__ __forceinline__ void gemm_body(
    const __half* __restrict__ Ah, int lda,
    const __half* __restrict__ Bh, const __half* __restrict__ Bl, int ldb,
    int K,
    float* __restrict__ C, int ldc,
    __half* __restrict__ Ch, __half* __restrict__ Cl,
    const float* __restrict__ bias)
{
    extern __shared__ char dsm_raw[];
    const uint32_t sb = (smem_u32(dsm_raw) + 1023u) & ~1023u;

    const int tid  = threadIdx.x;
    const int wid  = tid >> 5;
    const int lane = tid & 31;
    const int warp_m = wid & 1;       // 2 in M (64 rows each)
    const int warp_n = wid >> 1;      // 4 in N (64 cols each)

    float acc[4][8][4];
#pragma unroll
    for (int i = 0; i < 4; i++)
#pragma unroll
        for (int j = 0; j < 8; j++)
#pragma unroll
            for (int q = 0; q < 4; q++) acc[i][j][q] = 0.f;

    // cp.async mapping (rows are 64B = 32 halves)
    const int rA0 = tid >> 2, gA = tid & 3;
    const uint32_t dA0 = swz(rA0, gA), dA1 = swz(rA0 + 64, gA);
    const size_t aoff0 = (size_t)rA0 * lda + gA * 8;
    const size_t aoff1 = (size_t)(rA0 + 64) * lda + gA * 8;
    uint32_t dB[4];
    size_t boff[4];
#pragma unroll
    for (int j = 0; j < 4; j++) {
        const int r = rA0 + 64 * j;
        dB[j] = swz(r, gA);
        boff[j] = (size_t)r * ldb + gA * 8;
    }

#define LOAD_STAGE(st, kidx) do { \
    const int k0 = (kidx) * BK; \
    const uint32_t sd = sb + (st) * STAGE_BY; \
    cpa16(sd + OFF_AH + dA0, Ah + aoff0 + k0); \
    cpa16(sd + OFF_AH + dA1, Ah + aoff1 + k0); \
    cpa16(sd + OFF_BH + dB[0], Bh + boff[0] + k0); \
    cpa16(sd + OFF_BH + dB[1], Bh + boff[1] + k0); \
    cpa16(sd + OFF_BH + dB[2], Bh + boff[2] + k0); \
    cpa16(sd + OFF_BH + dB[3], Bh + boff[3] + k0); \
    cpa16(sd + OFF_BL + dB[0], Bl + boff[0] + k0); \
    cpa16(sd + OFF_BL + dB[1], Bl + boff[1] + k0); \
    cpa16(sd + OFF_BL + dB[2], Bl + boff[2] + k0); \
    cpa16(sd + OFF_BL + dB[3], Bl + boff[3] + k0); \
} while (0)

    const int kt = K / BK;
#pragma unroll
    for (int s = 0; s < STAGES - 1; s++) {
        LOAD_STAGE(s, s);
        CP_COMMIT();
    }

    const uint32_t a_row = warp_m * 64 + (lane & 7) + (((lane >> 3) & 1) << 3);
    const uint32_t a_gb  = lane >> 4;
    const uint32_t b_row = warp_n * 64 + (lane & 7) + ((lane >> 4) << 3);
    const uint32_t b_gb  = (lane >> 3) & 1;

    for (int it = 0; it < kt; it++) {
        CP_WAIT(STAGES - 2);
        __syncthreads();

        const int nf = it + STAGES - 1;
        if (nf < kt) LOAD_STAGE(nf % STAGES, nf);
        CP_COMMIT();

        const uint32_t st = sb + (it % STAGES) * STAGE_BY;
#pragma unroll
        for (int ks = 0; ks < 2; ks++) {
            const uint32_t ag = ks * 2 + a_gb;
            const uint32_t bg = ks * 2 + b_gb;
            uint32_t ah[4][4];
#pragma unroll
            for (int mt = 0; mt < 4; mt++)
                LDSM4(ah[mt], st + OFF_AH + swz(a_row + mt * 16, ag));
#pragma unroll
            for (int nc = 0; nc < 4; nc++) {        // 4 chunks of n16
                uint32_t bh[4], bl[4];
                const uint32_t bd = st + swz(b_row + nc * 16, bg);
                LDSM4(bh, bd + OFF_BH);
                LDSM4(bl, bd + OFF_BL);
#pragma unroll
                for (int mt = 0; mt < 4; mt++)
#pragma unroll
                    for (int h = 0; h < 2; h++) {   // n8 halves
                        float* a4 = acc[mt][nc * 2 + h];
                        mma_f16(a4, ah[mt], bh[h * 2], bh[h * 2 + 1]);
                        mma_f16(a4, ah[mt], bl[h * 2], bl[h * 2 + 1]);
                    }
            }
        }
    }
#undef LOAD_STAGE

    // Epilogue
#pragma unroll
    for (int mt = 0; mt < 4; mt++) {
        const int r = warp_m * 64 + mt * 16 + (lane >> 2);
#pragma unroll
        for (int nt = 0; nt < 8; nt++) {
            const int c = warp_n * 64 + nt * 8 + (lane & 3) * 2;
            float v00 = acc[mt][nt][0], v01 = acc[mt][nt][1];
            float v10 = acc[mt][nt][2], v11 = acc[mt][nt][3];
            if (EPI == 0 || EPI == 2 || EPI == 3) {
                float2 bb = __ldg((const float2*)(bias + c));
                v00 += bb.x; v01 += bb.y; v10 += bb.x; v11 += bb.y;
            }
            if (EPI == 2) {
                __half2 l0, l1;
                __half2 h0 = split_hl(v00, v01, l0);
                __half2 h1 = split_hl(v10, v11, l1);
                *(__half2*)(Ch + (size_t)r * ldc + c) = h0;
                *(__half2*)(Ch + (size_t)(r + 8) * ldc + c) = h1;
                *(__half2*)(Cl + (size_t)r * ldc + c) = l0;
                *(__half2*)(Cl + (size_t)(r + 8) * ldc + c) = l1;
            } else if (EPI == 3) {
                *(__half2*)(Ch + (size_t)r * ldc + c) =
                    __halves2half2(__float2half_rn(v00), __float2half_rn(v01));
                *(__half2*)(Ch + (size_t)(r + 8) * ldc + c) =
                    __halves2half2(__float2half_rn(v10), __float2half_rn(v11));
            } else {
                float2 s;
                s.x = v00; s.y = v01;
                *(float2*)(C + (size_t)r * ldc + c) = s;
                s.x = v10; s.y = v11;
                *(float2*)(C + (size_t)(r + 8) * ldc + c) = s;
            }
        }
    }
}

// Supertile remap for L2 reuse (G must divide gridDim.y)
__device__ __forceinline__ void remap_xy(int G, int& bx, int& by) {
    int lin = blockIdx.y * gridDim.x + blockIdx.x;
    int per = G * gridDim.x;
    int grp = lin / per, rem = lin % per;
    by = grp * G + (rem % G);
    bx = rem / G;
}

// ---------------------------------------------------------------------------
// GEMM kernels (CTA tile 128M x 256N)
// ---------------------------------------------------------------------------
__global__ void __launch_bounds__(256, 1)
proj_q_kernel(const float* __restrict__ bias)
{
    int bx, by; remap_xy(8, bx, by);
    const int tm = by * 128, tn = bx * 256;
    gemm_body<3>(g_xh + (size_t)tm * D_MODEL, D_MODEL,
                 g_wqh + (size_t)tn * D_MODEL, g_wql + (size_t)tn * D_MODEL, D_MODEL,
                 D_MODEL, nullptr, TWO_D,
                 g_qh + (size_t)tm * TWO_D + tn, nullptr, bias + tn);
}

__global__ void __launch_bounds__(256, 1)
proj_k_kernel(const float* __restrict__ bias)
{
    int bx, by; remap_xy(8, bx, by);
    const int tm = by * 128, tn = bx * 256;
    gemm_body<2>(g_xh + (size_t)tm * D_MODEL, D_MODEL,
                 g_wkh + (size_t)tn * D_MODEL, g_wkl + (size_t)tn * D_MODEL, D_MODEL,
                 D_MODEL, nullptr, TWO_D,
                 g_kh + (size_t)tm * TWO_D + tn, g_kl + (size_t)tm * TWO_D + tn,
                 bias + tn);
}

__global__ void __launch_bounds__(256, 1)
proj_v_kernel(const float* __restrict__ bias)
{
    int bx, by; remap_xy(8, bx, by);
    const int tm = by * 128, tn = bx * 256;
    gemm_body<0>(g_xh + (size_t)tm * D_MODEL, D_MODEL,
                 g_wvh + (size_t)tn * D_MODEL, g_wvl + (size_t)tn * D_MODEL, D_MODEL,
                 D_MODEL, g_v + (size_t)tm * TWO_D + tn, TWO_D,
                 nullptr, nullptr, bias + tn);
}

__global__ void __launch_bounds__(256, 1)
logits_kernel()
{
    const int bz = blockIdx.z;
    const int b = bz >> 1, pair = bz & 1;
    const int tm = blockIdx.y * 128, tn = blockIdx.x * 256;
    const size_t qoff = (size_t)b * SEQ * TWO_D + (size_t)pair * D_MODEL;
    float* C = (pair ? g_l2 : g_l1) + (size_t)b * SEQ * SEQ
             + (size_t)tm * SEQ + tn;
    gemm_body<1>(g_qh + qoff + (size_t)tm * TWO_D, TWO_D,
                 g_kh + qoff + (size_t)tn * TWO_D, g_kl + qoff + (size_t)tn * TWO_D, TWO_D,
                 D_MODEL, C, SEQ, nullptr, nullptr, nullptr);
}

__global__ void __launch_bounds__(256, 1)
out_gemm_kernel(float* __restrict__ out)
{
    const int b = blockIdx.z;
    int bx, by; remap_xy(4, bx, by);
    const int tm = by * 128, tn = bx * 256;
    const size_t soff = (size_t)b * SEQ * SEQ + (size_t)tm * SEQ;
    const size_t voff = (size_t)b * TWO_D * SEQ + (size_t)tn * SEQ;
    gemm_body<1>(g_sch + soff, SEQ,
                 g_vth + voff, g_vtl + voff, SEQ,
                 SEQ, out + (size_t)b * SEQ * TWO_D + (size_t)tm * TWO_D + tn, TWO_D,
                 nullptr, nullptr, nullptr);
}

// ---------------------------------------------------------------------------
// Support kernels
// ---------------------------------------------------------------------------
// x: hi only (A operand)
__global__ void __launch_bounds__(256)
conv_x_kernel(const float* __restrict__ src, int n4)
{
    int idx = blockIdx.x * 256 + threadIdx.x;
    if (idx >= n4) return;
    float4 v = ((const float4*)src)[idx];
    __half2* hp = (__half2*)(g_xh + (size_t)idx * 4);
    hp[0] = __halves2half2(__float2half_rn(v.x), __float2half_rn(v.y));
    hp[1] = __halves2half2(__float2half_rn(v.z), __float2half_rn(v.w));
}

// weights: hi + lo (B operands); grid.z picks q/k/v
__global__ void __launch_bounds__(256)
conv_w_kernel(const float* __restrict__ wq, const float* __restrict__ wk,
              const float* __restrict__ wv, int n4)
{
    int idx = blockIdx.x * 256 + threadIdx.x;
    if (idx >= n4) return;
    const int z = blockIdx.z;
    const float* src = (z == 0) ? wq : (z == 1) ? wk : wv;
    __half* h = (z == 0) ? g_wqh : (z == 1) ? g_wkh : g_wvh;
    __half* l = (z == 0) ? g_wql : (z == 1) ? g_wkl : g_wvl;
    float4 v = ((const float4*)src)[idx];
    __half2 l0, l1;
    __half2 h0 = split_hl(v.x, v.y, l0);
    __half2 h1 = split_hl(v.z, v.w, l1);
    __half2* hp = (__half2*)(h + (size_t)idx * 4);
    hp[0] = h0; hp[1] = h1;
    __half2* lp = (__half2*)(l + (size_t)idx * 4);
    lp[0] = l0; lp[1] = l1;
}

// vt[b][n][s] = v[b][s][n], split to f16 hi/lo (B operand of out GEMM)
__global__ void __launch_bounds__(256)
transpose_v_kernel()
{
    __shared__ float t[32][33];
    const int b = blockIdx.z;
    const int s0 = blockIdx.y * 32, n0 = blockIdx.x * 32;
    const float* src = g_v + (size_t)b * SEQ * TWO_D;
    const int tx = threadIdx.x, ty = threadIdx.y;
#pragma unroll
    for (int i = ty; i < 32; i += 8)
        t[i][tx] = src[(size_t)(s0 + i) * TWO_D + n0 + tx];
    __syncthreads();
#pragma unroll
    for (int i = ty; i < 32; i += 8) {
        float v = t[tx][i];
        __half hh = __float2half_rn(v);
        size_t o = (size_t)b * TWO_D * SEQ + (size_t)(n0 + i) * SEQ + s0 + tx;
        g_vth[o] = hh;
        g_vtl[o] = __float2half_rn(v - __half2float(hh));
    }
}

// Softmax over key axis + differential combine; writes f16 hi scores (A operand)
__global__ void __launch_bounds__(256)
softmax_combine_kernel(const float* __restrict__ lq1, const float* __restrict__ lk1,
                       const float* __restrict__ lq2, const float* __restrict__ lk2)
{
    const int r = blockIdx.x, b = blockIdx.y;
    const size_t off = ((size_t)b * SEQ + r) * SEQ;
    const float scale = 0.04419417382415922f;  // 1/sqrt(512)
    const int tid = threadIdx.x;
    const int lane = tid & 31, warp = tid >> 5;

    float v1a = g_l1[off + tid]       * scale;
    float v1b = g_l1[off + tid + 256] * scale;
    float v2a = g_l2[off + tid]       * scale;
    float v2b = g_l2[off + tid + 256] * scale;

    __shared__ float red1[8], red2[8];

    float m1 = fmaxf(v1a, v1b), m2 = fmaxf(v2a, v2b);
#pragma unroll
    for (int o = 16; o; o >>= 1) {
        m1 = fmaxf(m1, __shfl_xor_sync(0xffffffffu, m1, o));
        m2 = fmaxf(m2, __shfl_xor_sync(0xffffffffu, m2, o));
    }
    if (lane == 0) { red1[warp] = m1; red2[warp] = m2; }
    __syncthreads();
    m1 = red1[0]; m2 = red2[0];
#pragma unroll
    for (int i = 1; i < 8; i++) { m1 = fmaxf(m1, red1[i]); m2 = fmaxf(m2, red2[i]); }
    __syncthreads();

    float e1a = expf(v1a - m1), e1b = expf(v1b - m1);
    float e2a = expf(v2a - m2), e2b = expf(v2b - m2);
    float s1 = e1a + e1b, s2 = e2a + e2b;
#pragma unroll
    for (int o = 16; o; o >>= 1) {
        s1 += __shfl_xor_sync(0xffffffffu, s1, o);
        s2 += __shfl_xor_sync(0xffffffffu, s2, o);
    }
    if (lane == 0) { red1[warp] = s1; red2[warp] = s2; }
    __syncthreads();
    s1 = 0.f; s2 = 0.f;
#pragma unroll
    for (int i = 0; i < 8; i++) { s1 += red1[i]; s2 += red2[i]; }
    const float inv1 = 1.f / s1, inv2 = 1.f / s2;

#pragma unroll
    for (int half = 0; half < 2; half++) {
        const int k = tid + half * 256;
        float e1 = half ? e1b : e1a;
        float e2 = half ? e2b : e2a;
        float lam = expf(lq1[k] * lk1[k]) - expf(lq2[k] * lk2[k]) + LAMBDA_INIT;
        float v = e1 * inv1 - lam * (e2 * inv2);
        g_sch[off + k] = __float2half_rn(v);
    }
}

// ---------------------------------------------------------------------------
extern "C" void kernel_launch(void* const* d_in, const int* in_sizes, int n_in,
                              void* d_out, int out_size)
{
    const float* x    = (const float*)d_in[0];
    const float* wq_w = (const float*)d_in[1];
    const float* wq_b = (const float*)d_in[2];
    const float* wk_w = (const float*)d_in[3];
    const float* wk_b = (const float*)d_in[4];
    const float* wv_w = (const float*)d_in[5];
    const float* wv_b = (const float*)d_in[6];
    const float* lq1  = (const float*)d_in[7];
    const float* lk1  = (const float*)d_in[8];
    const float* lq2  = (const float*)d_in[9];
    const float* lk2  = (const float*)d_in[10];
    float* out = (float*)d_out;

    cudaFuncSetAttribute(proj_q_kernel,   cudaFuncAttributeMaxDynamicSharedMemorySize, DSMEM_BYTES);
    cudaFuncSetAttribute(proj_k_kernel,   cudaFuncAttributeMaxDynamicSharedMemorySize, DSMEM_BYTES);
    cudaFuncSetAttribute(proj_v_kernel,   cudaFuncAttributeMaxDynamicSharedMemorySize, DSMEM_BYTES);
    cudaFuncSetAttribute(logits_kernel,   cudaFuncAttributeMaxDynamicSharedMemorySize, DSMEM_BYTES);
    cudaFuncSetAttribute(out_gemm_kernel, cudaFuncAttributeMaxDynamicSharedMemorySize, DSMEM_BYTES);

    const int n4x = 4096 * 4096 / 4;
    const int n4w = TWO_D * 4096 / 4;

    conv_x_kernel<<<n4x / 256, 256>>>(x, n4x);                              // 0
    conv_w_kernel<<<dim3(n4w / 256, 1, 3), 256>>>(wq_w, wk_w, wv_w, n4w);   // 1

    dim3 projGrid(TWO_D / 256, (NB * SEQ) / 128);                           // (32, 32)
    proj_q_kernel<<<projGrid, 256, DSMEM_BYTES>>>(wq_b);                    // 2
    proj_k_kernel<<<projGrid, 256, DSMEM_BYTES>>>(wk_b);                    // 3 <- profiled
    proj_v_kernel<<<projGrid, 256, DSMEM_BYTES>>>(wv_b);                    // 4

    dim3 trGrid(TWO_D / 32, SEQ / 32, NB);
    transpose_v_kernel<<<trGrid, dim3(32, 8)>>>();                          // 5

    dim3 logitsGrid(SEQ / 256, SEQ / 128, NB * 2);                          // (2, 4, 16)
    logits_kernel<<<logitsGrid, 256, DSMEM_BYTES>>>();                      // 6

    dim3 smGrid(SEQ, NB);
    softmax_combine_kernel<<<smGrid, 256>>>(lq1, lk1, lq2, lk2);            // 7

    dim3 outGrid(TWO_D / 256, SEQ / 128, NB);                               // (32, 4, 8)
    out_gemm_kernel<<<outGrid, 256, DSMEM_BYTES>>>(out);                    // 8
}